// round 16
// baseline (speedup 1.0000x reference)
#include <cuda_runtime.h>
#include <cuda_fp16.h>
#include <cstdint>

#define VOCAB 100000
#define EMBED 128
#define ROWS  12800   // 64*200
#define K_ITEMS 50

// 25.6 MB scratch: transposed weights WT[V][E] in fp16. Row 0 is zeroed by
// the transpose so the gather needs no id!=0 mask.
__device__ __align__(256) __half g_WT[(size_t)VOCAB * EMBED];

// ---------------------------------------------------------------------------
// Kernel A: transpose W [E=128, V=100000] (fp32) -> WT [V, E] (fp16).
// EXACT R14 version — measured AT the DRAM roofline (76.8 MB @ 7.9 TB/s):
// 32 E x 160 V tile, float4 global loads, scalar smem stores with bank map
// v*32 + ((e + v + (v>>2)) & 31) (conflict-free both phases), __stwt WT
// stores (write-through). Row v==0 zeroed (column 0 masked).
// ---------------------------------------------------------------------------
#define VT 160        // v per tile
#define F4T 40        // float4 per e-row per tile
#define ET 32         // e per tile

__device__ __forceinline__ int swz(int v, int e) {
    return v * 32 + ((e + v + (v >> 2)) & 31);
}

__global__ __launch_bounds__(256) void transpose_W(const float4* __restrict__ W4) {
    __shared__ float s[VT * 32];   // 20 KB

    const int tid = threadIdx.x;
    const int vt4 = blockIdx.x * F4T;    // float4 offset along V
    const int vt  = blockIdx.x * VT;     // float offset along V
    const int et  = blockIdx.y * ET;     // float offset along E

    #pragma unroll
    for (int i = 0; i < 5; i++) {
        const int idx = i * 256 + tid;
        const int e = idx / F4T;          // 0..31
        const int c = idx % F4T;          // 0..39
        const float4 w = W4[(size_t)(et + e) * (VOCAB / 4) + vt4 + c];
        const int v = 4 * c;
        s[swz(v + 0, e)] = w.x;
        s[swz(v + 1, e)] = w.y;
        s[swz(v + 2, e)] = w.z;
        s[swz(v + 3, e)] = w.w;
    }
    __syncthreads();

    uint2* WT_u2 = (uint2*)g_WT;          // 8 B = 4 halves per element
    #pragma unroll
    for (int i = 0; i < 5; i++) {
        const int idx = i * 256 + tid;
        const int v  = idx >> 3;          // 0..159
        const int e4 = idx & 7;           // 0..7
        const int e  = 4 * e4;
        __half2 h0 = __floats2half2_rn(s[swz(v, e + 0)], s[swz(v, e + 1)]);
        __half2 h1 = __floats2half2_rn(s[swz(v, e + 2)], s[swz(v, e + 3)]);
        uint2 o;
        o.x = *reinterpret_cast<unsigned int*>(&h0);
        o.y = *reinterpret_cast<unsigned int*>(&h1);
        if (vt + v == 0) { o.x = 0u; o.y = 0u; }   // mask column 0
        __stwt(&WT_u2[(size_t)(vt + v) * (EMBED / 4) + (et >> 2) + e4], o);
    }
}

// ---------------------------------------------------------------------------
// Kernel B: embedding-bag gather from fp16 WT. EXACT R14 code (measured best,
// 15.3us, 40 regs) + PDL: launched with programmatic stream serialization so
// the first wave dispatches during the transpose tail, stages its ids, and
// only then blocks on cudaGridDependencySynchronize() before touching WT.
// 3200 blocks x 128 thr (4 rows/block, warp per row). Half-warp fetches one
// full 256 B WT row via LDG.128 (2 ids/iter, 25 iters in 5 groups of 5).
// fp16 HADD2 within a group, fp32 across groups. Branch-free; shfl_xor(16)
// merges half-warp partials; out stored with .cs.
// ---------------------------------------------------------------------------
#define ROWS_PER_BLOCK 4
#define THREADS_B (ROWS_PER_BLOCK * 32)

__global__ __launch_bounds__(THREADS_B) void gather_rows(
    const int* __restrict__ ids,         // [ROWS, 50] int32
    const float* __restrict__ bias,      // [128] fp32
    float* __restrict__ out)             // [ROWS, 128] fp32
{
    __shared__ int s_ids[ROWS_PER_BLOCK][K_ITEMS];

    const int tid  = threadIdx.x;
    const int lane = tid & 31;
    const int wrow = tid >> 5;
    const int row0 = blockIdx.x * ROWS_PER_BLOCK;
    const int sub  = lane & 15;          // lane within half-warp
    const int half = lane >> 4;          // which id of the pair

    // WT-independent prologue: stage ids while the transpose may still run.
    const int* gids = ids + (size_t)row0 * K_ITEMS;
    #pragma unroll
    for (int i = tid; i < ROWS_PER_BLOCK * K_ITEMS; i += THREADS_B) {
        s_ids[i / K_ITEMS][i % K_ITEMS] = gids[i];
    }

    // PDL sync: wait until the transpose grid's memory is visible.
    cudaGridDependencySynchronize();
    __syncthreads();

    float a0 = 0.f, a1 = 0.f, a2 = 0.f, a3 = 0.f;
    float a4 = 0.f, a5 = 0.f, a6 = 0.f, a7 = 0.f;

    #pragma unroll
    for (int g = 0; g < 5; g++) {
        const __half2 z = __float2half2_rn(0.f);
        __half2 h0 = z, h1 = z, h2 = z, h3 = z;

        #pragma unroll
        for (int j = 0; j < 5; j++) {
            const int v = s_ids[wrow][10 * g + 2 * j + half];
            const int4 r = __ldg((const int4*)(g_WT + (size_t)v * EMBED) + sub);
            h0 = __hadd2(h0, *reinterpret_cast<const __half2*>(&r.x));
            h1 = __hadd2(h1, *reinterpret_cast<const __half2*>(&r.y));
            h2 = __hadd2(h2, *reinterpret_cast<const __half2*>(&r.z));
            h3 = __hadd2(h3, *reinterpret_cast<const __half2*>(&r.w));
        }

        const float2 f0 = __half22float2(h0);
        const float2 f1 = __half22float2(h1);
        const float2 f2 = __half22float2(h2);
        const float2 f3 = __half22float2(h3);
        a0 += f0.x; a1 += f0.y; a2 += f1.x; a3 += f1.y;
        a4 += f2.x; a5 += f2.y; a6 += f3.x; a7 += f3.y;
    }

    // Merge the two half-warp partial sums (each covered different ids).
    a0 += __shfl_xor_sync(0xffffffffu, a0, 16);
    a1 += __shfl_xor_sync(0xffffffffu, a1, 16);
    a2 += __shfl_xor_sync(0xffffffffu, a2, 16);
    a3 += __shfl_xor_sync(0xffffffffu, a3, 16);
    a4 += __shfl_xor_sync(0xffffffffu, a4, 16);
    a5 += __shfl_xor_sync(0xffffffffu, a5, 16);
    a6 += __shfl_xor_sync(0xffffffffu, a6, 16);
    a7 += __shfl_xor_sync(0xffffffffu, a7, 16);

    // Lane writes float4 slot j = 2*sub + half (dims 8*sub + 4*half ..+3).
    const int j = 2 * sub + half;
    float4 o = (half == 0) ? make_float4(a0, a1, a2, a3)
                           : make_float4(a4, a5, a6, a7);
    const float4 bv = __ldg((const float4*)bias + j);
    o.x += bv.x; o.y += bv.y; o.z += bv.z; o.w += bv.w;
    __stcs((float4*)(out + (size_t)(row0 + wrow) * EMBED) + j, o);
}

// ---------------------------------------------------------------------------
// Entry point. Inputs (metadata order): content_input int32, W f32, b f32.
// Gather launched with programmatic stream serialization (PDL) so its
// prologue overlaps the transpose tail; correctness is guaranteed by the
// cudaGridDependencySynchronize() in the gather before any WT read.
// ---------------------------------------------------------------------------
extern "C" void kernel_launch(void* const* d_in, const int* in_sizes, int n_in,
                              void* d_out, int out_size) {
    const int*   ids = (const int*)d_in[0];
    const float* W   = (const float*)d_in[1];
    const float* b   = (const float*)d_in[2];
    float*       out = (float*)d_out;

    dim3 tgrid(VOCAB / VT, EMBED / ET);   // 625 x 4
    transpose_W<<<tgrid, 256>>>((const float4*)W);

    cudaLaunchConfig_t cfg = {};
    cfg.gridDim  = dim3(ROWS / ROWS_PER_BLOCK, 1, 1);
    cfg.blockDim = dim3(THREADS_B, 1, 1);
    cfg.dynamicSmemBytes = 0;
    cfg.stream = 0;
    cudaLaunchAttribute attr[1];
    attr[0].id = cudaLaunchAttributeProgrammaticStreamSerialization;
    attr[0].val.programmaticStreamSerializationAllowed = 1;
    cfg.attrs = attr;
    cfg.numAttrs = 1;
    cudaLaunchKernelEx(&cfg, gather_rows, ids, b, out);
}

// round 17
// speedup vs baseline: 1.4069x; 1.4069x over previous
#include <cuda_runtime.h>
#include <cuda_fp16.h>
#include <cstdint>

#define VOCAB 100000
#define EMBED 128
#define ROWS  12800   // 64*200
#define K_ITEMS 50

// 25.6 MB scratch: transposed weights WT[V][E] in fp16. Row 0 is zeroed by
// the transpose so the gather needs no id!=0 mask.
__device__ __align__(256) __half g_WT[(size_t)VOCAB * EMBED];

// ---------------------------------------------------------------------------
// Kernel A: transpose W [E=128, V=100000] (fp32) -> WT [V, E] (fp16).
// EXACT R14 version — measured AT the DRAM roofline (76.8 MB @ 7.9 TB/s):
// 32 E x 160 V tile, float4 global loads, scalar smem stores with bank map
// v*32 + ((e + v + (v>>2)) & 31) (conflict-free both phases), __stwt WT
// stores (write-through: the 25.6 MB DRAM write lands in this read-bound
// window, not as dirty writebacks during the gather). Row v==0 zeroed.
// ---------------------------------------------------------------------------
#define VT 160        // v per tile
#define F4T 40        // float4 per e-row per tile
#define ET 32         // e per tile

__device__ __forceinline__ int swz(int v, int e) {
    return v * 32 + ((e + v + (v >> 2)) & 31);
}

__global__ __launch_bounds__(256) void transpose_W(const float4* __restrict__ W4) {
    __shared__ float s[VT * 32];   // 20 KB

    const int tid = threadIdx.x;
    const int vt4 = blockIdx.x * F4T;    // float4 offset along V
    const int vt  = blockIdx.x * VT;     // float offset along V
    const int et  = blockIdx.y * ET;     // float offset along E

    #pragma unroll
    for (int i = 0; i < 5; i++) {
        const int idx = i * 256 + tid;
        const int e = idx / F4T;          // 0..31
        const int c = idx % F4T;          // 0..39
        const float4 w = W4[(size_t)(et + e) * (VOCAB / 4) + vt4 + c];
        const int v = 4 * c;
        s[swz(v + 0, e)] = w.x;
        s[swz(v + 1, e)] = w.y;
        s[swz(v + 2, e)] = w.z;
        s[swz(v + 3, e)] = w.w;
    }
    __syncthreads();

    uint2* WT_u2 = (uint2*)g_WT;          // 8 B = 4 halves per element
    #pragma unroll
    for (int i = 0; i < 5; i++) {
        const int idx = i * 256 + tid;
        const int v  = idx >> 3;          // 0..159
        const int e4 = idx & 7;           // 0..7
        const int e  = 4 * e4;
        __half2 h0 = __floats2half2_rn(s[swz(v, e + 0)], s[swz(v, e + 1)]);
        __half2 h1 = __floats2half2_rn(s[swz(v, e + 2)], s[swz(v, e + 3)]);
        uint2 o;
        o.x = *reinterpret_cast<unsigned int*>(&h0);
        o.y = *reinterpret_cast<unsigned int*>(&h1);
        if (vt + v == 0) { o.x = 0u; o.y = 0u; }   // mask column 0
        __stwt(&WT_u2[(size_t)(vt + v) * (EMBED / 4) + (et >> 2) + e4], o);
    }
}

// ---------------------------------------------------------------------------
// Kernel B: embedding-bag gather from fp16 WT (EXACT R14/R10 config: measured
// best at 15.3us). 3200 blocks x 128 thr (4 rows/block, warp per row).
// Half-warp fetches one full 256 B WT row via LDG.128 (2 ids/iteration,
// 25 iterations in 5 groups of 5). fp16 HADD2 within a group, fp32 across
// groups. Branch-free (WT row 0 zero). shfl_xor(16) merges half-warp
// partials. Out stored with .cs (single-use).
// ---------------------------------------------------------------------------
#define ROWS_PER_BLOCK 4
#define THREADS_B (ROWS_PER_BLOCK * 32)

__global__ __launch_bounds__(THREADS_B) void gather_rows(
    const int* __restrict__ ids,         // [ROWS, 50] int32
    const float* __restrict__ bias,      // [128] fp32
    float* __restrict__ out)             // [ROWS, 128] fp32
{
    __shared__ int s_ids[ROWS_PER_BLOCK][K_ITEMS];

    const int tid  = threadIdx.x;
    const int lane = tid & 31;
    const int wrow = tid >> 5;
    const int row0 = blockIdx.x * ROWS_PER_BLOCK;
    const int sub  = lane & 15;          // lane within half-warp
    const int half = lane >> 4;          // which id of the pair

    const int* gids = ids + (size_t)row0 * K_ITEMS;
    #pragma unroll
    for (int i = tid; i < ROWS_PER_BLOCK * K_ITEMS; i += THREADS_B) {
        s_ids[i / K_ITEMS][i % K_ITEMS] = gids[i];
    }
    __syncthreads();

    float a0 = 0.f, a1 = 0.f, a2 = 0.f, a3 = 0.f;
    float a4 = 0.f, a5 = 0.f, a6 = 0.f, a7 = 0.f;

    #pragma unroll
    for (int g = 0; g < 5; g++) {
        const __half2 z = __float2half2_rn(0.f);
        __half2 h0 = z, h1 = z, h2 = z, h3 = z;

        #pragma unroll
        for (int j = 0; j < 5; j++) {
            const int v = s_ids[wrow][10 * g + 2 * j + half];
            const int4 r = __ldg((const int4*)(g_WT + (size_t)v * EMBED) + sub);
            h0 = __hadd2(h0, *reinterpret_cast<const __half2*>(&r.x));
            h1 = __hadd2(h1, *reinterpret_cast<const __half2*>(&r.y));
            h2 = __hadd2(h2, *reinterpret_cast<const __half2*>(&r.z));
            h3 = __hadd2(h3, *reinterpret_cast<const __half2*>(&r.w));
        }

        const float2 f0 = __half22float2(h0);
        const float2 f1 = __half22float2(h1);
        const float2 f2 = __half22float2(h2);
        const float2 f3 = __half22float2(h3);
        a0 += f0.x; a1 += f0.y; a2 += f1.x; a3 += f1.y;
        a4 += f2.x; a5 += f2.y; a6 += f3.x; a7 += f3.y;
    }

    // Merge the two half-warp partial sums (each covered different ids).
    a0 += __shfl_xor_sync(0xffffffffu, a0, 16);
    a1 += __shfl_xor_sync(0xffffffffu, a1, 16);
    a2 += __shfl_xor_sync(0xffffffffu, a2, 16);
    a3 += __shfl_xor_sync(0xffffffffu, a3, 16);
    a4 += __shfl_xor_sync(0xffffffffu, a4, 16);
    a5 += __shfl_xor_sync(0xffffffffu, a5, 16);
    a6 += __shfl_xor_sync(0xffffffffu, a6, 16);
    a7 += __shfl_xor_sync(0xffffffffu, a7, 16);

    // Lane writes float4 slot j = 2*sub + half (dims 8*sub + 4*half ..+3).
    const int j = 2 * sub + half;
    float4 o = (half == 0) ? make_float4(a0, a1, a2, a3)
                           : make_float4(a4, a5, a6, a7);
    const float4 bv = __ldg((const float4*)bias + j);
    o.x += bv.x; o.y += bv.y; o.z += bv.z; o.w += bv.w;
    __stcs((float4*)(out + (size_t)(row0 + wrow) * EMBED) + j, o);
}

// ---------------------------------------------------------------------------
// Entry point. Inputs (metadata order): content_input int32, W f32, b f32.
// ---------------------------------------------------------------------------
extern "C" void kernel_launch(void* const* d_in, const int* in_sizes, int n_in,
                              void* d_out, int out_size) {
    const int*   ids = (const int*)d_in[0];
    const float* W   = (const float*)d_in[1];
    const float* b   = (const float*)d_in[2];
    float*       out = (float*)d_out;

    dim3 tgrid(VOCAB / VT, EMBED / ET);   // 625 x 4
    transpose_W<<<tgrid, 256>>>((const float4*)W);

    gather_rows<<<ROWS / ROWS_PER_BLOCK, THREADS_B>>>(ids, b, out);
}